// round 15
// baseline (speedup 1.0000x reference)
#include <cuda_runtime.h>
#include <cuda_bf16.h>
#include <cstdint>

#define N_NODES 200000
#define C 256
#define VC 16
#define VD 3
#define M_SEG 50000

// float4 counts: [s_sum | v_sum | cnt]
#define S_SUM_F4 (M_SEG * (C / 4))            // 3,200,000
#define V_SUM_F4 (M_SEG * (VC * VD / 4))      // 600,000
#define CNT_F4   (M_SEG / 4)                  // 12,500
#define TOT_F4   (S_SUM_F4 + V_SUM_F4 + CNT_F4)

__device__ float4        g_acc[TOT_F4];       // 61 MB, L2-resident for RED
__device__ int           g_seg_is64;
__device__ __nv_bfloat16 g_whi[C * C];        // Ws split hi, [n][k] row-major
__device__ __nv_bfloat16 g_wlo[C * C];        // Ws split lo

// ---------------------------------------------------------------------------
// Fused zero + int64/int32 detection (JAX may silently downcast motif_batch).
// ---------------------------------------------------------------------------
__global__ void zero_detect_k(const unsigned long long* __restrict__ p) {
    int idx = blockIdx.x * blockDim.x + threadIdx.x;
    if (idx < TOT_F4) g_acc[idx] = make_float4(0.f, 0.f, 0.f, 0.f);
    if (blockIdx.x == 0 && threadIdx.x == 0) {
        int is64 = 1;
        #pragma unroll
        for (int i = 0; i < 16; i++) {
            if ((p[i] >> 32) != 0ULL) { is64 = 0; }
        }
        g_seg_is64 = is64;
    }
}

__device__ __forceinline__ int get_seg(const void* segp, int node, int is64) {
    if (is64) return (int)((const long long*)segp)[node];
    return ((const int*)segp)[node];
}

__device__ __forceinline__ void red_add_v4(float* p, float4 v) {
    asm volatile("red.global.add.v4.f32 [%0], {%1,%2,%3,%4};"
                 :: "l"(p), "f"(v.x), "f"(v.y), "f"(v.z), "f"(v.w) : "memory");
}

__device__ __forceinline__ void red_add_f32(float* p, float v) {
    asm volatile("red.global.add.f32 [%0], %1;" :: "l"(p), "f"(v) : "memory");
}

__global__ void scatter_k(const float4* __restrict__ s4,
                          const float4* __restrict__ v4,
                          const void*   __restrict__ segp) {
    int idx = blockIdx.x * blockDim.x + threadIdx.x;
    int is64 = g_seg_is64;

    if (idx < N_NODES * (C / 4)) {
        int node = idx >> 6;
        int q    = idx & 63;
        int m    = get_seg(segp, node, is64);
        float4 val = s4[idx];
        red_add_v4((float*)&g_acc[m * 64 + q], val);
    }
    if (idx < N_NODES * (VC * VD / 4)) {
        int node = idx / 12;
        int q    = idx - node * 12;
        int m    = get_seg(segp, node, is64);
        float4 val = v4[idx];
        red_add_v4((float*)&g_acc[S_SUM_F4 + m * 12 + q], val);
    }
    if (idx < N_NODES) {
        int m = get_seg(segp, idx, is64);
        float* cnt = (float*)&g_acc[S_SUM_F4 + V_SUM_F4];
        red_add_f32(cnt + m, 1.0f);
    }
}

// ---------------------------------------------------------------------------
// Split Ws (fp32, [out][in] row-major) into bf16 hi + lo.
// ---------------------------------------------------------------------------
__global__ void prep_w_k(const float* __restrict__ Ws) {
    int i = blockIdx.x * blockDim.x + threadIdx.x;
    if (i < C * C) {
        float w = Ws[i];
        __nv_bfloat16 h = __float2bfloat16(w);
        float hf = __bfloat162float(h);
        g_whi[i] = h;
        g_wlo[i] = __float2bfloat16(w - hf);
    }
}

// ---------------------------------------------------------------------------
// PTX helpers (baseline PTX only — compiles under compute_103)
// ---------------------------------------------------------------------------
__device__ __forceinline__ uint32_t smem_u32(const void* p) {
    uint32_t a;
    asm("{ .reg .u64 t; cvta.to.shared.u64 t, %1; cvt.u32.u64 %0, t; }"
        : "=r"(a) : "l"(p));
    return a;
}

#define LDMATRIX_X4(r0, r1, r2, r3, addr) \
    asm volatile("ldmatrix.sync.aligned.m8n8.x4.shared.b16 {%0,%1,%2,%3}, [%4];" \
                 : "=r"(r0), "=r"(r1), "=r"(r2), "=r"(r3) : "r"(addr))

#define LDMATRIX_X2(r0, r1, addr) \
    asm volatile("ldmatrix.sync.aligned.m8n8.x2.shared.b16 {%0,%1}, [%2];" \
                 : "=r"(r0), "=r"(r1) : "r"(addr))

#define MMA_BF16(c, a, b) \
    asm volatile("mma.sync.aligned.m16n8k16.row.col.f32.bf16.bf16.f32 " \
                 "{%0,%1,%2,%3}, {%4,%5,%6,%7}, {%8,%9}, {%0,%1,%2,%3};" \
                 : "+f"((c)[0]), "+f"((c)[1]), "+f"((c)[2]), "+f"((c)[3]) \
                 : "r"((a)[0]), "r"((a)[1]), "r"((a)[2]), "r"((a)[3]), \
                   "r"((b)[0]), "r"((b)[1]))

#define CP_ASYNC16(dst, src) \
    asm volatile("cp.async.cg.shared.global [%0], [%1], 16;" \
                 :: "r"(dst), "l"(src) : "memory")
#define CP_COMMIT asm volatile("cp.async.commit_group;" ::: "memory")
#define CP_WAIT0  asm volatile("cp.async.wait_group 0;" ::: "memory")

// ---------------------------------------------------------------------------
// s_out = (s_sum/cnt) @ Ws^T + bs via bf16-split mma.sync (3 products).
// CTA 128M x 128N, 8 warps (2M x 4N), K chunks of 32, double-buffered smem,
// ONE __syncthreads per chunk. A prefetched to regs; B via cp.async.
// __launch_bounds__(256, 2): 2 CTAs/SM (R14: occ 22.7%, regs 128).
// R15: MMA loop is PRODUCT-MAJOR — 16 independent accumulators per pass
// instead of 3-long RAW chains per (mi,ni) (R14: issue 19.4%, tensor 43%).
// Smem pitch 40 bf16 (80 B): ldmatrix row segments hit disjoint bank quads.
// ---------------------------------------------------------------------------
#define AP 40
#define BUF_B   40960u               // bytes per buffer (4 arrays x 10240)
#define AH_B(b) ((b) * BUF_B)
#define AL_B(b) ((b) * BUF_B + 10240u)
#define BH_B(b) ((b) * BUF_B + 20480u)
#define BL_B(b) ((b) * BUF_B + 30720u)
#define FS_SMEM (2 * BUF_B)          // 81920 bytes

__global__ void __launch_bounds__(256, 2) finish_s_mma(const float* __restrict__ bs,
                                                       float* __restrict__ out) {
    extern __shared__ __nv_bfloat16 sm[];
    int tid  = threadIdx.x;
    int wid  = tid >> 5, lane = tid & 31;
    int m0   = blockIdx.x * 128;
    int n0   = blockIdx.y * 128;
    int wm   = (wid >> 2) * 64;
    int wn   = (wid & 3) * 32;

    int lr = tid >> 1;              // 0..127 staging row
    int lk = (tid & 1) * 16;        // k offset within 32-wide chunk

    int   arow = m0 + lr;
    const float* cntp = (const float*)(g_acc + S_SUM_F4 + V_SUM_F4);
    float inv = 0.f;
    if (arow < M_SEG) inv = 1.0f / fmaxf(cntp[arow], 1.0f);
    const float4* A4 = (const float4*)g_acc;

    uint32_t smb = smem_u32(sm);
    uint32_t stA = (uint32_t)(lr * AP + lk) * 2;   // staging byte offset in array
    const char* gBh = (const char*)(g_whi + (size_t)(n0 + lr) * C);
    const char* gBl = (const char*)(g_wlo + (size_t)(n0 + lr) * C);

    float acc[4][4][4];
    #pragma unroll
    for (int i = 0; i < 4; i++)
        #pragma unroll
        for (int j = 0; j < 4; j++)
            #pragma unroll
            for (int q = 0; q < 4; q++) acc[i][j][q] = 0.f;

    // ldmatrix lane geometry (same mapping as validated R12 kernel)
    int a_r = wm + (lane & 15);
    int a_c = (lane >> 4) * 8;
    int b_r = wn + (lane & 7);
    int b_c = ((lane >> 3) & 1) * 8;

    float4 av[4];

    // ---- prologue: stage chunk 0 into buffer 0 ----
    {
        const float4* Ag = A4 + (size_t)arow * 64 + (tid & 1) * 4;
        #pragma unroll
        for (int q = 0; q < 4; q++)
            av[q] = (arow < M_SEG) ? Ag[q] : make_float4(0.f, 0.f, 0.f, 0.f);

        uint32_t dh = smb + BH_B(0) + stA;
        uint32_t dl = smb + BL_B(0) + stA;
        const char* sh = gBh + (size_t)lk * 2;
        const char* sl = gBl + (size_t)lk * 2;
        CP_ASYNC16(dh, sh);      CP_ASYNC16(dh + 16, sh + 16);
        CP_ASYNC16(dl, sl);      CP_ASYNC16(dl + 16, sl + 16);
        CP_COMMIT;

        uint32_t* ah = (uint32_t*)((char*)sm + AH_B(0) + stA);
        uint32_t* al = (uint32_t*)((char*)sm + AL_B(0) + stA);
        #pragma unroll
        for (int q = 0; q < 4; q++) {
            float4 a = av[q];
            a.x *= inv; a.y *= inv; a.z *= inv; a.w *= inv;
            __nv_bfloat162 h0 = __float22bfloat162_rn(make_float2(a.x, a.y));
            __nv_bfloat162 h1 = __float22bfloat162_rn(make_float2(a.z, a.w));
            __nv_bfloat162 e0 = __float22bfloat162_rn(make_float2(
                a.x - __low2float(h0), a.y - __high2float(h0)));
            __nv_bfloat162 e1 = __float22bfloat162_rn(make_float2(
                a.z - __low2float(h1), a.w - __high2float(h1)));
            ah[2 * q]     = *(uint32_t*)&h0;
            ah[2 * q + 1] = *(uint32_t*)&h1;
            al[2 * q]     = *(uint32_t*)&e0;
            al[2 * q + 1] = *(uint32_t*)&e1;
        }
        CP_WAIT0;
        __syncthreads();
    }

    #pragma unroll
    for (int ch = 0; ch < 8; ch++) {
        int b = ch & 1;

        // ---- prefetch chunk ch+1 (A regs + B cp.async) while computing ----
        if (ch < 7) {
            const float4* Ag = A4 + (size_t)arow * 64 + (ch + 1) * 8 + (tid & 1) * 4;
            #pragma unroll
            for (int q = 0; q < 4; q++)
                av[q] = (arow < M_SEG) ? Ag[q] : make_float4(0.f, 0.f, 0.f, 0.f);

            int nb = (ch + 1) & 1;
            uint32_t dh = smb + BH_B(nb) + stA;
            uint32_t dl = smb + BL_B(nb) + stA;
            const char* sh = gBh + (size_t)((ch + 1) * 32 + lk) * 2;
            const char* sl = gBl + (size_t)((ch + 1) * 32 + lk) * 2;
            CP_ASYNC16(dh, sh);      CP_ASYNC16(dh + 16, sh + 16);
            CP_ASYNC16(dl, sl);      CP_ASYNC16(dl + 16, sl + 16);
            CP_COMMIT;
        }

        // ---- compute on buffer b: product-major MMA order for ILP ----
        {
            uint32_t abh = smb + AH_B(b);
            uint32_t abl = smb + AL_B(b);
            uint32_t bbh = smb + BH_B(b);
            uint32_t bbl = smb + BL_B(b);
            #pragma unroll
            for (int k16 = 0; k16 < 2; k16++) {
                int kof = k16 * 16;
                uint32_t ah[4][4], al[4][4], bh[4][2], bl[4][2];
                #pragma unroll
                for (int mi = 0; mi < 4; mi++) {
                    uint32_t addr = (uint32_t)(((a_r + mi * 16) * AP + kof + a_c) * 2);
                    LDMATRIX_X4(ah[mi][0], ah[mi][1], ah[mi][2], ah[mi][3], abh + addr);
                    LDMATRIX_X4(al[mi][0], al[mi][1], al[mi][2], al[mi][3], abl + addr);
                }
                #pragma unroll
                for (int ni = 0; ni < 4; ni++) {
                    uint32_t addr = (uint32_t)(((b_r + ni * 8) * AP + kof + b_c) * 2);
                    LDMATRIX_X2(bh[ni][0], bh[ni][1], bbh + addr);
                    LDMATRIX_X2(bl[ni][0], bl[ni][1], bbl + addr);
                }
                // pass 1: A_hi * B_hi — 16 independent accumulators
                #pragma unroll
                for (int mi = 0; mi < 4; mi++)
                    #pragma unroll
                    for (int ni = 0; ni < 4; ni++)
                        MMA_BF16(acc[mi][ni], ah[mi], bh[ni]);
                // pass 2: A_hi * B_lo
                #pragma unroll
                for (int mi = 0; mi < 4; mi++)
                    #pragma unroll
                    for (int ni = 0; ni < 4; ni++)
                        MMA_BF16(acc[mi][ni], ah[mi], bl[ni]);
                // pass 3: A_lo * B_hi
                #pragma unroll
                for (int mi = 0; mi < 4; mi++)
                    #pragma unroll
                    for (int ni = 0; ni < 4; ni++)
                        MMA_BF16(acc[mi][ni], al[mi], bh[ni]);
            }
        }

        // ---- convert prefetched A into next buffer, single barrier ----
        if (ch < 7) {
            int nb = (ch + 1) & 1;
            uint32_t* ah = (uint32_t*)((char*)sm + AH_B(nb) + stA);
            uint32_t* al = (uint32_t*)((char*)sm + AL_B(nb) + stA);
            #pragma unroll
            for (int q = 0; q < 4; q++) {
                float4 a = av[q];
                a.x *= inv; a.y *= inv; a.z *= inv; a.w *= inv;
                __nv_bfloat162 h0 = __float22bfloat162_rn(make_float2(a.x, a.y));
                __nv_bfloat162 h1 = __float22bfloat162_rn(make_float2(a.z, a.w));
                __nv_bfloat162 e0 = __float22bfloat162_rn(make_float2(
                    a.x - __low2float(h0), a.y - __high2float(h0)));
                __nv_bfloat162 e1 = __float22bfloat162_rn(make_float2(
                    a.z - __low2float(h1), a.w - __high2float(h1)));
                ah[2 * q]     = *(uint32_t*)&h0;
                ah[2 * q + 1] = *(uint32_t*)&h1;
                al[2 * q]     = *(uint32_t*)&e0;
                al[2 * q + 1] = *(uint32_t*)&e1;
            }
            CP_WAIT0;
            __syncthreads();
        }
    }

    // ---- epilogue: add bias, write ----
    #pragma unroll
    for (int ni = 0; ni < 4; ni++) {
        int col = n0 + wn + ni * 8 + (lane & 3) * 2;
        float2 bb = *(const float2*)&bs[col];
        #pragma unroll
        for (int mi = 0; mi < 4; mi++) {
            int r0 = m0 + wm + mi * 16 + (lane >> 2);
            if (r0 < M_SEG) {
                float2 o = make_float2(acc[mi][ni][0] + bb.x,
                                       acc[mi][ni][1] + bb.y);
                *(float2*)&out[(size_t)r0 * C + col] = o;
            }
            if (r0 + 8 < M_SEG) {
                float2 o = make_float2(acc[mi][ni][2] + bb.x,
                                       acc[mi][ni][3] + bb.y);
                *(float2*)&out[(size_t)(r0 + 8) * C + col] = o;
            }
        }
    }
}

// ---------------------------------------------------------------------------
// v_out[m,o,d] = (1/cnt_m) * sum_c v_sum[m,c,d] * Wv[o,c] + bv[o]
// ---------------------------------------------------------------------------
__global__ void __launch_bounds__(256) finish_v_k(const float* __restrict__ Wv,
                                                  const float* __restrict__ bv,
                                                  float* __restrict__ vout) {
    __shared__ float vs[16][48];
    __shared__ float wv[16][16];
    __shared__ float bvs[16];
    __shared__ float invs[16];

    int tid = threadIdx.x;
    int mbase = blockIdx.x * 16;
    const float* vsum = (const float*)(g_acc + S_SUM_F4);
    const float* cntp = (const float*)(g_acc + S_SUM_F4 + V_SUM_F4);

    for (int i = tid; i < 16 * 48; i += 256) {
        int mi = i / 48, q = i - mi * 48;
        vs[mi][q] = vsum[(size_t)(mbase + mi) * 48 + q];
    }
    wv[tid >> 4][tid & 15] = Wv[tid];
    if (tid < 16) {
        bvs[tid]  = bv[tid];
        invs[tid] = 1.0f / fmaxf(cntp[mbase + tid], 1.0f);
    }
    __syncthreads();

    int mi = tid >> 4;
    int o  = tid & 15;
    float a0 = 0.f, a1 = 0.f, a2 = 0.f;
    #pragma unroll
    for (int c = 0; c < 16; c++) {
        float w = wv[o][c];
        a0 += vs[mi][c * 3 + 0] * w;
        a1 += vs[mi][c * 3 + 1] * w;
        a2 += vs[mi][c * 3 + 2] * w;
    }
    int mm = mbase + mi;
    float inv = invs[mi];
    float b = bvs[o];
    size_t base = (size_t)mm * 48 + o * 3;
    vout[base + 0] = a0 * inv + b;
    vout[base + 1] = a1 * inv + b;
    vout[base + 2] = a2 * inv + b;
}

// ---------------------------------------------------------------------------
extern "C" void kernel_launch(void* const* d_in, const int* in_sizes, int n_in,
                              void* d_out, int out_size) {
    const float4* s4  = (const float4*)d_in[0];
    const float4* v4  = (const float4*)d_in[1];
    const void*   seg = d_in[2];
    const float*  Ws  = (const float*)d_in[3];
    const float*  bs  = (const float*)d_in[4];
    const float*  Wv  = (const float*)d_in[5];
    const float*  bv  = (const float*)d_in[6];

    float* out   = (float*)d_out;
    float* s_out = out;
    float* v_out = out + (size_t)M_SEG * C;

    static int smem_set = 0;
    if (!smem_set) {
        cudaFuncSetAttribute(finish_s_mma,
                             cudaFuncAttributeMaxDynamicSharedMemorySize, FS_SMEM);
        smem_set = 1;
    }

    // launch order puts finish_s_mma at profile slot 3
    zero_detect_k<<<(TOT_F4 + 255) / 256, 256>>>((const unsigned long long*)seg);
    prep_w_k<<<(C * C + 255) / 256, 256>>>(Ws);
    scatter_k<<<(N_NODES * (C / 4) + 255) / 256, 256>>>(s4, v4, seg);

    dim3 gs((M_SEG + 127) / 128, C / 128);
    finish_s_mma<<<gs, 256, FS_SMEM>>>(bs, s_out);
    finish_v_k<<<M_SEG / 16, 256>>>(Wv, bv, v_out);
}

// round 16
// speedup vs baseline: 1.1258x; 1.1258x over previous
#include <cuda_runtime.h>
#include <cuda_bf16.h>
#include <cuda_fp16.h>
#include <cstdint>

#define N_NODES 200000
#define C 256
#define VC 16
#define VD 3
#define M_SEG 50000

// float4 counts: [s_sum | v_sum | cnt]
#define S_SUM_F4 (M_SEG * (C / 4))            // 3,200,000
#define V_SUM_F4 (M_SEG * (VC * VD / 4))      // 600,000
#define CNT_F4   (M_SEG / 4)                  // 12,500
#define TOT_F4   (S_SUM_F4 + V_SUM_F4 + CNT_F4)

__device__ float4 g_acc[TOT_F4];              // 61 MB, L2-resident for RED
__device__ int    g_seg_is64;
__device__ __half g_whi[C * C];               // Ws split hi (fp16), [n][k]
__device__ __half g_wlo[C * C];               // Ws split lo (fp16)

// ---------------------------------------------------------------------------
// Fused zero + int64/int32 detection (JAX may silently downcast motif_batch).
// ---------------------------------------------------------------------------
__global__ void zero_detect_k(const unsigned long long* __restrict__ p) {
    int idx = blockIdx.x * blockDim.x + threadIdx.x;
    if (idx < TOT_F4) g_acc[idx] = make_float4(0.f, 0.f, 0.f, 0.f);
    if (blockIdx.x == 0 && threadIdx.x == 0) {
        int is64 = 1;
        #pragma unroll
        for (int i = 0; i < 16; i++) {
            if ((p[i] >> 32) != 0ULL) { is64 = 0; }
        }
        g_seg_is64 = is64;
    }
}

__device__ __forceinline__ int get_seg(const void* segp, int node, int is64) {
    if (is64) return (int)((const long long*)segp)[node];
    return ((const int*)segp)[node];
}

__device__ __forceinline__ void red_add_v4(float* p, float4 v) {
    asm volatile("red.global.add.v4.f32 [%0], {%1,%2,%3,%4};"
                 :: "l"(p), "f"(v.x), "f"(v.y), "f"(v.z), "f"(v.w) : "memory");
}

__device__ __forceinline__ void red_add_f32(float* p, float v) {
    asm volatile("red.global.add.f32 [%0], %1;" :: "l"(p), "f"(v) : "memory");
}

__global__ void scatter_k(const float4* __restrict__ s4,
                          const float4* __restrict__ v4,
                          const void*   __restrict__ segp) {
    int idx = blockIdx.x * blockDim.x + threadIdx.x;
    int is64 = g_seg_is64;

    if (idx < N_NODES * (C / 4)) {
        int node = idx >> 6;
        int q    = idx & 63;
        int m    = get_seg(segp, node, is64);
        float4 val = s4[idx];
        red_add_v4((float*)&g_acc[m * 64 + q], val);
    }
    if (idx < N_NODES * (VC * VD / 4)) {
        int node = idx / 12;
        int q    = idx - node * 12;
        int m    = get_seg(segp, node, is64);
        float4 val = v4[idx];
        red_add_v4((float*)&g_acc[S_SUM_F4 + m * 12 + q], val);
    }
    if (idx < N_NODES) {
        int m = get_seg(segp, idx, is64);
        float* cnt = (float*)&g_acc[S_SUM_F4 + V_SUM_F4];
        red_add_f32(cnt + m, 1.0f);
    }
}

// ---------------------------------------------------------------------------
// Split Ws (fp32, [out][in] row-major) into fp16 hi + lo.
// |lo| ~ 2^-12 |w| may be fp16-subnormal; tensor cores accept fp16 subnormals.
// ---------------------------------------------------------------------------
__global__ void prep_w_k(const float* __restrict__ Ws) {
    int i = blockIdx.x * blockDim.x + threadIdx.x;
    if (i < C * C) {
        float w = Ws[i];
        __half h = __float2half_rn(w);
        float hf = __half2float(h);
        g_whi[i] = h;
        g_wlo[i] = __float2half_rn(w - hf);
    }
}

// ---------------------------------------------------------------------------
// PTX helpers (baseline PTX only — compiles under compute_103)
// ---------------------------------------------------------------------------
__device__ __forceinline__ uint32_t smem_u32(const void* p) {
    uint32_t a;
    asm("{ .reg .u64 t; cvta.to.shared.u64 t, %1; cvt.u32.u64 %0, t; }"
        : "=r"(a) : "l"(p));
    return a;
}

#define LDMATRIX_X4(r0, r1, r2, r3, addr) \
    asm volatile("ldmatrix.sync.aligned.m8n8.x4.shared.b16 {%0,%1,%2,%3}, [%4];" \
                 : "=r"(r0), "=r"(r1), "=r"(r2), "=r"(r3) : "r"(addr))

#define LDMATRIX_X2(r0, r1, addr) \
    asm volatile("ldmatrix.sync.aligned.m8n8.x2.shared.b16 {%0,%1}, [%2];" \
                 : "=r"(r0), "=r"(r1) : "r"(addr))

#define MMA_F16(c, a, b) \
    asm volatile("mma.sync.aligned.m16n8k16.row.col.f32.f16.f16.f32 " \
                 "{%0,%1,%2,%3}, {%4,%5,%6,%7}, {%8,%9}, {%0,%1,%2,%3};" \
                 : "+f"((c)[0]), "+f"((c)[1]), "+f"((c)[2]), "+f"((c)[3]) \
                 : "r"((a)[0]), "r"((a)[1]), "r"((a)[2]), "r"((a)[3]), \
                   "r"((b)[0]), "r"((b)[1]))

#define CP_ASYNC16(dst, src) \
    asm volatile("cp.async.cg.shared.global [%0], [%1], 16;" \
                 :: "r"(dst), "l"(src) : "memory")
#define CP_COMMIT asm volatile("cp.async.commit_group;" ::: "memory")
#define CP_WAIT0  asm volatile("cp.async.wait_group 0;" ::: "memory")

// ---------------------------------------------------------------------------
// s_out = (s_sum/cnt) @ Ws^T + bs via fp16 weight-split mma.sync (2 products):
//   D = A16·Bh + A16·Bl    (A single fp16; dropped eps_A·B term ~2^-12 rel)
// CTA 128M x 128N, 8 warps (2M x 4N), K chunks of 32, double-buffered smem,
// ONE __syncthreads per chunk. A prefetched to regs; B via cp.async.
// __launch_bounds__(256, 2): 2 CTAs/SM. vs R15: HMMA count x2/3, LDSM x2/3.
// Smem pitch 40 halves (80 B): ldmatrix rows hit disjoint bank quads.
// ---------------------------------------------------------------------------
#define AP 40
#define ARR_B   10240u               // one 128x32 fp16 array, pitch 40
#define BUF_B   30720u               // bytes per buffer (3 arrays)
#define A_B(b)  ((b) * BUF_B)
#define BH_B(b) ((b) * BUF_B + 10240u)
#define BL_B(b) ((b) * BUF_B + 20480u)
#define FS_SMEM (2 * BUF_B)          // 61440 bytes

__global__ void __launch_bounds__(256, 2) finish_s_mma(const float* __restrict__ bs,
                                                       float* __restrict__ out) {
    extern __shared__ __half sm[];
    int tid  = threadIdx.x;
    int wid  = tid >> 5, lane = tid & 31;
    int m0   = blockIdx.x * 128;
    int n0   = blockIdx.y * 128;
    int wm   = (wid >> 2) * 64;
    int wn   = (wid & 3) * 32;

    int lr = tid >> 1;              // 0..127 staging row
    int lk = (tid & 1) * 16;        // k offset within 32-wide chunk

    int   arow = m0 + lr;
    const float* cntp = (const float*)(g_acc + S_SUM_F4 + V_SUM_F4);
    float inv = 0.f;
    if (arow < M_SEG) inv = 1.0f / fmaxf(cntp[arow], 1.0f);
    const float4* A4 = (const float4*)g_acc;

    uint32_t smb = smem_u32(sm);
    uint32_t stA = (uint32_t)(lr * AP + lk) * 2;   // staging byte offset in array
    const char* gBh = (const char*)(g_whi + (size_t)(n0 + lr) * C);
    const char* gBl = (const char*)(g_wlo + (size_t)(n0 + lr) * C);

    float acc[4][4][4];
    #pragma unroll
    for (int i = 0; i < 4; i++)
        #pragma unroll
        for (int j = 0; j < 4; j++)
            #pragma unroll
            for (int q = 0; q < 4; q++) acc[i][j][q] = 0.f;

    // ldmatrix lane geometry (same mapping as validated R12 kernel)
    int a_r = wm + (lane & 15);
    int a_c = (lane >> 4) * 8;
    int b_r = wn + (lane & 7);
    int b_c = ((lane >> 3) & 1) * 8;

    float4 av[4];

    // ---- convert 4 float4 (16 k-values) to fp16 and store at stA ----
    auto stage_A = [&](int buf, const float4* src) {
        uint32_t* ap = (uint32_t*)((char*)sm + A_B(buf) + stA);
        #pragma unroll
        for (int q = 0; q < 4; q++) {
            float4 a = src[q];
            a.x *= inv; a.y *= inv; a.z *= inv; a.w *= inv;
            __half2 h0 = __floats2half2_rn(a.x, a.y);
            __half2 h1 = __floats2half2_rn(a.z, a.w);
            ap[2 * q]     = *(uint32_t*)&h0;
            ap[2 * q + 1] = *(uint32_t*)&h1;
        }
    };

    // ---- prologue: stage chunk 0 into buffer 0 ----
    {
        const float4* Ag = A4 + (size_t)arow * 64 + (tid & 1) * 4;
        #pragma unroll
        for (int q = 0; q < 4; q++)
            av[q] = (arow < M_SEG) ? Ag[q] : make_float4(0.f, 0.f, 0.f, 0.f);

        uint32_t dh = smb + BH_B(0) + stA;
        uint32_t dl = smb + BL_B(0) + stA;
        const char* sh = gBh + (size_t)lk * 2;
        const char* sl = gBl + (size_t)lk * 2;
        CP_ASYNC16(dh, sh);      CP_ASYNC16(dh + 16, sh + 16);
        CP_ASYNC16(dl, sl);      CP_ASYNC16(dl + 16, sl + 16);
        CP_COMMIT;

        stage_A(0, av);
        CP_WAIT0;
        __syncthreads();
    }

    #pragma unroll
    for (int ch = 0; ch < 8; ch++) {
        int b = ch & 1;

        // ---- prefetch chunk ch+1 (A regs + B cp.async) while computing ----
        if (ch < 7) {
            const float4* Ag = A4 + (size_t)arow * 64 + (ch + 1) * 8 + (tid & 1) * 4;
            #pragma unroll
            for (int q = 0; q < 4; q++)
                av[q] = (arow < M_SEG) ? Ag[q] : make_float4(0.f, 0.f, 0.f, 0.f);

            int nb = (ch + 1) & 1;
            uint32_t dh = smb + BH_B(nb) + stA;
            uint32_t dl = smb + BL_B(nb) + stA;
            const char* sh = gBh + (size_t)((ch + 1) * 32 + lk) * 2;
            const char* sl = gBl + (size_t)((ch + 1) * 32 + lk) * 2;
            CP_ASYNC16(dh, sh);      CP_ASYNC16(dh + 16, sh + 16);
            CP_ASYNC16(dl, sl);      CP_ASYNC16(dl + 16, sl + 16);
            CP_COMMIT;
        }

        // ---- compute on buffer b: 2 product passes ----
        {
            uint32_t aba = smb + A_B(b);
            uint32_t bbh = smb + BH_B(b);
            uint32_t bbl = smb + BL_B(b);
            #pragma unroll
            for (int k16 = 0; k16 < 2; k16++) {
                int kof = k16 * 16;
                uint32_t af[4][4], bh[4][2], bl[4][2];
                #pragma unroll
                for (int mi = 0; mi < 4; mi++) {
                    uint32_t addr = (uint32_t)(((a_r + mi * 16) * AP + kof + a_c) * 2);
                    LDMATRIX_X4(af[mi][0], af[mi][1], af[mi][2], af[mi][3], aba + addr);
                }
                #pragma unroll
                for (int ni = 0; ni < 4; ni++) {
                    uint32_t addr = (uint32_t)(((b_r + ni * 8) * AP + kof + b_c) * 2);
                    LDMATRIX_X2(bh[ni][0], bh[ni][1], bbh + addr);
                    LDMATRIX_X2(bl[ni][0], bl[ni][1], bbl + addr);
                }
                // pass 1: A * B_hi
                #pragma unroll
                for (int mi = 0; mi < 4; mi++)
                    #pragma unroll
                    for (int ni = 0; ni < 4; ni++)
                        MMA_F16(acc[mi][ni], af[mi], bh[ni]);
                // pass 2: A * B_lo
                #pragma unroll
                for (int mi = 0; mi < 4; mi++)
                    #pragma unroll
                    for (int ni = 0; ni < 4; ni++)
                        MMA_F16(acc[mi][ni], af[mi], bl[ni]);
            }
        }

        // ---- convert prefetched A into next buffer, single barrier ----
        if (ch < 7) {
            stage_A((ch + 1) & 1, av);
            CP_WAIT0;
            __syncthreads();
        }
    }

    // ---- epilogue: add bias, write ----
    #pragma unroll
    for (int ni = 0; ni < 4; ni++) {
        int col = n0 + wn + ni * 8 + (lane & 3) * 2;
        float2 bb = *(const float2*)&bs[col];
        #pragma unroll
        for (int mi = 0; mi < 4; mi++) {
            int r0 = m0 + wm + mi * 16 + (lane >> 2);
            if (r0 < M_SEG) {
                float2 o = make_float2(acc[mi][ni][0] + bb.x,
                                       acc[mi][ni][1] + bb.y);
                *(float2*)&out[(size_t)r0 * C + col] = o;
            }
            if (r0 + 8 < M_SEG) {
                float2 o = make_float2(acc[mi][ni][2] + bb.x,
                                       acc[mi][ni][3] + bb.y);
                *(float2*)&out[(size_t)(r0 + 8) * C + col] = o;
            }
        }
    }
}

// ---------------------------------------------------------------------------
// v_out[m,o,d] = (1/cnt_m) * sum_c v_sum[m,c,d] * Wv[o,c] + bv[o]
// ---------------------------------------------------------------------------
__global__ void __launch_bounds__(256) finish_v_k(const float* __restrict__ Wv,
                                                  const float* __restrict__ bv,
                                                  float* __restrict__ vout) {
    __shared__ float vs[16][48];
    __shared__ float wv[16][16];
    __shared__ float bvs[16];
    __shared__ float invs[16];

    int tid = threadIdx.x;
    int mbase = blockIdx.x * 16;
    const float* vsum = (const float*)(g_acc + S_SUM_F4);
    const float* cntp = (const float*)(g_acc + S_SUM_F4 + V_SUM_F4);

    for (int i = tid; i < 16 * 48; i += 256) {
        int mi = i / 48, q = i - mi * 48;
        vs[mi][q] = vsum[(size_t)(mbase + mi) * 48 + q];
    }
    wv[tid >> 4][tid & 15] = Wv[tid];
    if (tid < 16) {
        bvs[tid]  = bv[tid];
        invs[tid] = 1.0f / fmaxf(cntp[mbase + tid], 1.0f);
    }
    __syncthreads();

    int mi = tid >> 4;
    int o  = tid & 15;
    float a0 = 0.f, a1 = 0.f, a2 = 0.f;
    #pragma unroll
    for (int c = 0; c < 16; c++) {
        float w = wv[o][c];
        a0 += vs[mi][c * 3 + 0] * w;
        a1 += vs[mi][c * 3 + 1] * w;
        a2 += vs[mi][c * 3 + 2] * w;
    }
    int mm = mbase + mi;
    float inv = invs[mi];
    float b = bvs[o];
    size_t base = (size_t)mm * 48 + o * 3;
    vout[base + 0] = a0 * inv + b;
    vout[base + 1] = a1 * inv + b;
    vout[base + 2] = a2 * inv + b;
}

// ---------------------------------------------------------------------------
extern "C" void kernel_launch(void* const* d_in, const int* in_sizes, int n_in,
                              void* d_out, int out_size) {
    const float4* s4  = (const float4*)d_in[0];
    const float4* v4  = (const float4*)d_in[1];
    const void*   seg = d_in[2];
    const float*  Ws  = (const float*)d_in[3];
    const float*  bs  = (const float*)d_in[4];
    const float*  Wv  = (const float*)d_in[5];
    const float*  bv  = (const float*)d_in[6];

    float* out   = (float*)d_out;
    float* s_out = out;
    float* v_out = out + (size_t)M_SEG * C;

    static int smem_set = 0;
    if (!smem_set) {
        cudaFuncSetAttribute(finish_s_mma,
                             cudaFuncAttributeMaxDynamicSharedMemorySize, FS_SMEM);
        smem_set = 1;
    }

    // launch order puts finish_s_mma at profile slot 3
    zero_detect_k<<<(TOT_F4 + 255) / 256, 256>>>((const unsigned long long*)seg);
    prep_w_k<<<(C * C + 255) / 256, 256>>>(Ws);
    scatter_k<<<(N_NODES * (C / 4) + 255) / 256, 256>>>(s4, v4, seg);

    dim3 gs((M_SEG + 127) / 128, C / 128);
    finish_s_mma<<<gs, 256, FS_SMEM>>>(bs, s_out);
    finish_v_k<<<M_SEG / 16, 256>>>(Wv, bv, v_out);
}